// round 15
// baseline (speedup 1.0000x reference)
#include <cuda_runtime.h>
#include <math.h>

// ---------------- output layout (float32, tuple order) ----------------
#define N_RECON   (16ULL*64*256*256)          // 67108864
#define OFF_Q     (N_RECON)
#define N_Q       (16ULL*4096*128)            // 8388608
#define OFF_IDX   (OFF_Q + N_Q)               // 75497472
#define N_IDX     (16ULL*4096)
#define OFF_LOSS  (OFF_IDX + N_IDX)           // 75563008

// ---------------- scratch (device globals; no allocation) ----------------
__device__ float g_s2[16ULL*128*128*128];   // fused(spec+e1) out [16,128,128,128]
__device__ float g_s3[16ULL*256*64*64];     // e2 out             [16,256,64,64]
__device__ float g_tok[16ULL*128*64*64];    // proj out (tokens, NCHW)
__device__ float g_fin[16ULL*64*64*64];     // final 1x1 conv at low res
__device__ int   g_idx[16*4096];
__device__ float g_wt_e1[128*9*128];        // e1 transposed [(h,ky,kx)][oc]
__device__ float g_wt_f[64*9*128];          // fused weights [(ic,ky,kx)][oc]
__device__ float g_tb[9*128];               // spec-bias tap table [kyx][oc]
__device__ float g_wt_e2[128*9*256];
__device__ float g_wt_proj[256*128];
__device__ float g_wt_rec[128*9*128];
__device__ float g_wt_fin[128*64];
__device__ float g_ct[128*1024];            // codebook transposed [k][j]
__device__ float g_cnorm[1024];
__device__ float g_ptab[1025ULL*9*128];     // rec-conv codeword table; row 1024 = zeros
__device__ double g_acc[2];                 // [0]=recon sq sum, [1]=vq sq sum

// ---------------- small helpers ----------------
__global__ void k_init() { g_acc[0] = 0.0; g_acc[1] = 0.0; }

// all weight transposes in one grid-stride launch: dst[r*Cout+oc] = src[oc*R+r]
__global__ void k_transpose_all(const float* __restrict__ w_e1, const float* __restrict__ w_e2,
                                const float* __restrict__ w_proj, const float* __restrict__ w_rec,
                                const float* __restrict__ w_fin, const float* __restrict__ cb)
{
    int i = blockIdx.x * blockDim.x + threadIdx.x;
    if (i < 147456) { int oc=i/1152, r=i-oc*1152; g_wt_e1[(size_t)r*128+oc]=w_e1[i]; return; }
    i -= 147456;
    if (i < 294912) { int oc=i/1152, r=i-oc*1152; g_wt_e2[(size_t)r*256+oc]=w_e2[i]; return; }
    i -= 294912;
    if (i < 32768)  { int oc=i/256,  r=i-oc*256;  g_wt_proj[(size_t)r*128+oc]=w_proj[i]; return; }
    i -= 32768;
    if (i < 147456) { int oc=i/1152, r=i-oc*1152; g_wt_rec[(size_t)r*128+oc]=w_rec[i]; return; }
    i -= 147456;
    if (i < 8192)   { int oc=i/128,  r=i-oc*128;  g_wt_fin[(size_t)r*64+oc]=w_fin[i]; return; }
    i -= 8192;
    if (i < 131072) { int oc=i/128,  r=i-oc*128;  g_ct[(size_t)r*1024+oc]=cb[i]; }
}
#define N_TRANS_ALL (147456+294912+32768+147456+8192+131072)

__global__ void k_comb(const float* __restrict__ w_spec)
{
    int ic = blockIdx.x, kyx = blockIdx.y, oc = threadIdx.x;
    float s = 0.f;
    #pragma unroll 8
    for (int h = 0; h < 128; h++)
        s = fmaf(g_wt_e1[(size_t)(h * 9 + kyx) * 128 + oc], w_spec[h * 64 + ic], s);
    g_wt_f[(size_t)(ic * 9 + kyx) * 128 + oc] = s;
}

__global__ void k_tapbias(const float* __restrict__ b_spec)
{
    int kyx = blockIdx.x, oc = threadIdx.x;
    float s = 0.f;
    #pragma unroll 8
    for (int h = 0; h < 128; h++)
        s = fmaf(g_wt_e1[(size_t)(h * 9 + kyx) * 128 + oc], b_spec[h], s);
    g_tb[kyx * 128 + oc] = s;
}

__global__ void k_cnorm(const float* __restrict__ cb)
{
    int j = blockIdx.x * blockDim.x + threadIdx.x;
    if (j < 1024) {
        float s = 0.f;
        #pragma unroll 8
        for (int k = 0; k < 128; k++) { float v = cb[j*128+k]; s = fmaf(v, v, s); }
        g_cnorm[j] = s;
    }
}

// rec-conv codeword table
__global__ void k_ptab(const float* __restrict__ cb)
{
    int j = blockIdx.x, kyx = blockIdx.y, oc = threadIdx.x;
    float s = 0.f;
    if (j < 1024) {
        #pragma unroll 8
        for (int c = 0; c < 128; c++)
            s = fmaf(g_wt_rec[(size_t)(c * 9 + kyx) * 128 + oc], cb[j * 128 + c], s);
    }
    g_ptab[((size_t)j * 9 + kyx) * 128 + oc] = s;
}

// ---------------- smem-tiled direct conv (scalar fp32 — proven) ----------------
template<int K, int S, int CHUNK, int TOC, bool RELU, bool FUSEB>
__global__ void k_conv_t(const float* __restrict__ in, const float* __restrict__ wt,
                         const float* __restrict__ bias, float* __restrict__ out,
                         int Cin, int Hin, int Win, int Hout, int Wout, int Cout, int nxc)
{
    constexpr int PAD   = (K == 3) ? 1 : 0;
    constexpr int SPAN  = 63 * S + K;
    constexpr int SPAD  = (SPAN + 3) & ~3;
    constexpr int VSPAN = 7 * S + K;
    constexpr int OCW   = TOC / 4;
    constexpr int NT    = OCW * 8;

    __shared__ __align__(16) float s_in[CHUNK][K][SPAD];
    __shared__ __align__(16) float s_w[CHUNK * K * K][TOC];

    const int t    = threadIdx.x;
    const int ocg  = t % OCW;
    const int px0  = (t / OCW) * 8;

    const int xc    = blockIdx.x % nxc;
    const int ocblk = blockIdx.x / nxc;
    const int oy    = blockIdx.y;
    const int b     = blockIdx.z;

    const int ix0 = xc * 64 * S - PAD;
    const int iy0 = oy * S - PAD;

    float acc[4][8];
    #pragma unroll
    for (int j = 0; j < 4; j++)
        #pragma unroll
        for (int p = 0; p < 8; p++) acc[j][p] = 0.f;

    const int nchunk = Cin / CHUNK;
    for (int cc = 0; cc < nchunk; cc++) {
        const int ic0 = cc * CHUNK;
        __syncthreads();
        for (int idx = t; idx < CHUNK * K * SPAN; idx += NT) {
            int ic  = idx / (K * SPAN);
            int rem = idx - ic * (K * SPAN);
            int ky  = rem / SPAN;
            int j   = rem - ky * SPAN;
            int iy = iy0 + ky;
            int ix = ix0 + j;
            float v = 0.f;
            if (iy >= 0 && iy < Hin && ix >= 0 && ix < Win)
                v = in[(((size_t)b * Cin + ic0 + ic) * Hin + iy) * Win + ix];
            s_in[ic][ky][j] = v;
        }
        const float* wsrc = wt + (size_t)(ic0 * K * K) * Cout + ocblk * TOC;
        for (int idx = t; idx < CHUNK * K * K * (TOC / 4); idx += NT) {
            int rr = idx / (TOC / 4);
            int c4 = idx - rr * (TOC / 4);
            float4 w = *(const float4*)(wsrc + (size_t)rr * Cout + c4 * 4);
            *(float4*)&s_w[rr][c4 * 4] = w;
        }
        __syncthreads();

        #pragma unroll
        for (int ic = 0; ic < CHUNK; ic++) {
            #pragma unroll
            for (int ky = 0; ky < K; ky++) {
                float v[VSPAN];
                #pragma unroll
                for (int i = 0; i < VSPAN; i++) v[i] = s_in[ic][ky][px0 * S + i];
                #pragma unroll
                for (int kx = 0; kx < K; kx++) {
                    float4 w = *(const float4*)&s_w[(ic * K + ky) * K + kx][4 * ocg];
                    #pragma unroll
                    for (int p = 0; p < 8; p++) {
                        float xv = v[p * S + kx];
                        acc[0][p] = fmaf(w.x, xv, acc[0][p]);
                        acc[1][p] = fmaf(w.y, xv, acc[1][p]);
                        acc[2][p] = fmaf(w.z, xv, acc[2][p]);
                        acc[3][p] = fmaf(w.w, xv, acc[3][p]);
                    }
                }
            }
        }
    }

    #pragma unroll
    for (int j = 0; j < 4; j++) {
        int oc = ocblk * TOC + ocg * 4 + j;
        float bv = bias[oc];
        float lsub = 0.f;
        if (FUSEB) {
            float t00 = g_tb[0*128+oc], t01 = g_tb[1*128+oc], t02 = g_tb[2*128+oc];
            float t10 = g_tb[3*128+oc], t11 = g_tb[4*128+oc], t12 = g_tb[5*128+oc];
            float t20 = g_tb[6*128+oc], t21 = g_tb[7*128+oc], t22 = g_tb[8*128+oc];
            float add = t10+t11+t12 + t20+t21+t22;
            lsub = t10 + t20;
            if (oy > 0) { add += t00+t01+t02; lsub += t00; }
            bv += add;
        }
        size_t o = (((size_t)b * Cout + oc) * Hout + oy) * Wout + xc * 64 + px0;
        float4 r0, r1;
        r0.x = acc[j][0] + bv; r0.y = acc[j][1] + bv;
        r0.z = acc[j][2] + bv; r0.w = acc[j][3] + bv;
        r1.x = acc[j][4] + bv; r1.y = acc[j][5] + bv;
        r1.z = acc[j][6] + bv; r1.w = acc[j][7] + bv;
        if (FUSEB && xc == 0 && px0 == 0) r0.x -= lsub;
        if (RELU) {
            r0.x = fmaxf(r0.x, 0.f); r0.y = fmaxf(r0.y, 0.f);
            r0.z = fmaxf(r0.z, 0.f); r0.w = fmaxf(r0.w, 0.f);
            r1.x = fmaxf(r1.x, 0.f); r1.y = fmaxf(r1.y, 0.f);
            r1.z = fmaxf(r1.z, 0.f); r1.w = fmaxf(r1.w, 0.f);
        }
        *(float4*)(out + o)     = r0;
        *(float4*)(out + o + 4) = r1;
    }
}

// ---------------- VQ fused: 16 tokens/block, 256 thr, 4 codes/thread ----------------
// argmin_j (||C_j||^2 - 2 z.C_j); writes idx + quantized outputs + vq loss.
__global__ void k_vq(const float* __restrict__ cb, float* __restrict__ out)
{
    int g  = blockIdx.x;            // 0..4095
    int b  = g >> 8;
    int p0 = (g & 255) << 4;        // 16 tokens, same y row (p0 mult of 16)
    int t  = threadIdx.x;           // 0..255
    int c4 = t * 4;                 // first code of this thread

    __shared__ __align__(16) float zs[16][132];   // [token][k]; 528 B row stride
    {
        int ch = t & 127, ph = (t >> 7) * 8;    // 8 tokens per half
        int y = p0 >> 6, x0 = (p0 & 63) + ph;
        const float* src = g_tok + (((size_t)(b * 128 + ch)) * 64 + y) * 64 + x0;
        #pragma unroll
        for (int p = 0; p < 8; p++) zs[ph + p][ch] = src[p];
    }
    __syncthreads();

    float acc[16][4];
    #pragma unroll
    for (int p = 0; p < 16; p++)
        #pragma unroll
        for (int j = 0; j < 4; j++) acc[p][j] = 0.f;

    for (int k = 0; k < 128; k += 4) {
        float4 w0 = *(const float4*)(g_ct + (size_t)(k+0) * 1024 + c4);
        float4 w1 = *(const float4*)(g_ct + (size_t)(k+1) * 1024 + c4);
        float4 w2 = *(const float4*)(g_ct + (size_t)(k+2) * 1024 + c4);
        float4 w3 = *(const float4*)(g_ct + (size_t)(k+3) * 1024 + c4);
        #pragma unroll
        for (int p = 0; p < 16; p++) {
            float4 z = *(const float4*)&zs[p][k];
            acc[p][0] = fmaf(w0.x, z.x, acc[p][0]); acc[p][1] = fmaf(w0.y, z.x, acc[p][1]);
            acc[p][2] = fmaf(w0.z, z.x, acc[p][2]); acc[p][3] = fmaf(w0.w, z.x, acc[p][3]);
            acc[p][0] = fmaf(w1.x, z.y, acc[p][0]); acc[p][1] = fmaf(w1.y, z.y, acc[p][1]);
            acc[p][2] = fmaf(w1.z, z.y, acc[p][2]); acc[p][3] = fmaf(w1.w, z.y, acc[p][3]);
            acc[p][0] = fmaf(w2.x, z.z, acc[p][0]); acc[p][1] = fmaf(w2.y, z.z, acc[p][1]);
            acc[p][2] = fmaf(w2.z, z.z, acc[p][2]); acc[p][3] = fmaf(w2.w, z.z, acc[p][3]);
            acc[p][0] = fmaf(w3.x, z.w, acc[p][0]); acc[p][1] = fmaf(w3.y, z.w, acc[p][1]);
            acc[p][2] = fmaf(w3.z, z.w, acc[p][2]); acc[p][3] = fmaf(w3.w, z.w, acc[p][3]);
        }
    }

    float cn[4];
    #pragma unroll
    for (int j = 0; j < 4; j++) cn[j] = g_cnorm[c4 + j];

    __shared__ float s_bd[8][16];
    __shared__ int   s_bi[8][16];
    __shared__ int   s_win[16];
    #pragma unroll
    for (int p = 0; p < 16; p++) {
        float bd = 3.4e38f; int bi = 0;
        #pragma unroll
        for (int j = 0; j < 4; j++) {
            float d = cn[j] - 2.f * acc[p][j];
            if (d < bd) { bd = d; bi = c4 + j; }
        }
        #pragma unroll
        for (int off = 16; off > 0; off >>= 1) {
            float od = __shfl_down_sync(0xffffffffu, bd, off);
            int   oi = __shfl_down_sync(0xffffffffu, bi, off);
            if (od < bd || (od == bd && oi < bi)) { bd = od; bi = oi; }
        }
        if ((t & 31) == 0) { s_bd[t >> 5][p] = bd; s_bi[t >> 5][p] = bi; }
    }
    __syncthreads();
    if (t < 16) {
        float bd = s_bd[0][t]; int bi = s_bi[0][t];
        #pragma unroll
        for (int w = 1; w < 8; w++) {
            float od = s_bd[w][t]; int oi = s_bi[w][t];
            if (od < bd || (od == bd && oi < bi)) { bd = od; bi = oi; }
        }
        int tokid = b * 4096 + p0 + t;
        g_idx[tokid] = bi;
        out[OFF_IDX + tokid] = (float)bi;
        s_win[t] = bi;
    }
    __syncthreads();

    // gather quantized rows, write output block, vq-loss partial
    float ls = 0.f;
    {
        int ch = t & 127, ph = (t >> 7) * 8;
        #pragma unroll
        for (int p = 0; p < 8; p++) {
            int pp = ph + p;
            float q = cb[(size_t)s_win[pp] * 128 + ch];
            out[OFF_Q + ((size_t)(b * 4096 + p0 + pp)) * 128 + ch] = q;
            float d = q - zs[pp][ch];
            ls = fmaf(d, d, ls);
        }
    }
    #pragma unroll
    for (int off = 16; off > 0; off >>= 1) ls += __shfl_down_sync(0xffffffffu, ls, off);
    __shared__ float sp[8];
    if ((t & 31) == 0) sp[t >> 5] = ls;
    __syncthreads();
    if (t == 0) {
        float s = 0.f;
        #pragma unroll
        for (int w = 0; w < 8; w++) s += sp[w];
        atomicAdd(&g_acc[1], (double)s);
    }
}

// ---------------- rec conv (codeword table) + fin 1x1 fused -> g_fin ----------------
// grid (64 y, 16 b), block 128. rec_s rows 68 floats (272 B, 16B-aligned stride).
__global__ void k_rec_fin(const float* __restrict__ b_rec, const float* __restrict__ b_fin)
{
    int t = threadIdx.x, y = blockIdx.x, b = blockIdx.y;
    __shared__ int sidx[3][66];                    // x in [-1,64], sentinel 1024
    __shared__ __align__(16) float rec_s[128][68]; // relu'd rec row [c][x]
    for (int i = t; i < 3 * 66; i += 128) {
        int r  = i / 66;
        int rx = i - r * 66 - 1;
        int ry = y - 1 + r;
        sidx[r][rx + 1] = (ry >= 0 && ry < 64 && rx >= 0 && rx < 64)
                          ? g_idx[b * 4096 + ry * 64 + rx] : 1024;
    }
    __syncthreads();
    // phase 1: rec row for channel t
    {
        float bv = b_rec[t];
        for (int x = 0; x < 64; x += 2) {
            float a0 = bv, a1 = bv;
            #pragma unroll
            for (int ky = 0; ky < 3; ky++) {
                #pragma unroll
                for (int kx = 0; kx < 3; kx++) {
                    int j0 = sidx[ky][x + kx];
                    int j1 = sidx[ky][x + 1 + kx];
                    a0 += g_ptab[((size_t)j0 * 9 + ky * 3 + kx) * 128 + t];
                    a1 += g_ptab[((size_t)j1 * 9 + ky * 3 + kx) * 128 + t];
                }
            }
            rec_s[t][x]     = fmaxf(a0, 0.f);
            rec_s[t][x + 1] = fmaxf(a1, 0.f);
        }
    }
    __syncthreads();
    // phase 2: fin 1x1 (128->64) on this row; thread: ocf = t&63, x-half = (t>>6)*32
    {
        int ocf = t & 63, xh = (t >> 6) * 32;
        float a[32];
        float bv = b_fin[ocf];
        #pragma unroll
        for (int i = 0; i < 32; i++) a[i] = bv;
        for (int c = 0; c < 128; c++) {
            float w = g_wt_fin[c * 64 + ocf];
            #pragma unroll
            for (int q = 0; q < 8; q++) {
                float4 r = *(const float4*)&rec_s[c][xh + 4 * q];
                a[4*q+0] = fmaf(w, r.x, a[4*q+0]);
                a[4*q+1] = fmaf(w, r.y, a[4*q+1]);
                a[4*q+2] = fmaf(w, r.z, a[4*q+2]);
                a[4*q+3] = fmaf(w, r.w, a[4*q+3]);
            }
        }
        float* dst = g_fin + (((size_t)(b * 64 + ocf)) * 64 + y) * 64 + xh;
        #pragma unroll
        for (int q = 0; q < 8; q++)
            *(float4*)(dst + 4 * q) = make_float4(a[4*q], a[4*q+1], a[4*q+2], a[4*q+3]);
    }
}

// ---------------- bilinear 4x upsample of g_fin (+recon loss) ----------------
__global__ void k_upsample(const float* __restrict__ x, float* __restrict__ out)
{
    int t  = threadIdx.x;
    int oc = t & 63;
    int xg = t >> 6;
    int xc = blockIdx.x, oy = blockIdx.y, b = blockIdx.z;

    float sy = (oy + 0.5f) * 0.25f - 0.5f;
    int   y0 = (int)floorf(sy);
    float fy = sy - (float)y0;
    int y0c = min(63, max(0, y0));
    int y1c = min(63, max(0, y0 + 1));

    __shared__ float sf[2][64][19];
    for (int idx = t; idx < 2 * 64 * 18; idx += 256) {
        int row = idx / (64 * 18);
        int rem = idx - row * 64 * 18;
        int c   = rem / 18;
        int sx  = rem - c * 18;
        int gx = min(63, max(0, 16 * xc - 1 + sx));
        int gy = row ? y1c : y0c;
        sf[row][c][sx] = g_fin[(((size_t)b * 64 + c) * 64 + gy) * 64 + gx];
    }
    __syncthreads();

    float ls = 0.f;
    size_t obase = (((size_t)b * 64 + oc) * 256 + oy) * 256 + 64 * xc + 16 * xg;
    const float* xr = x + obase;
    #pragma unroll
    for (int q = 0; q < 4; q++) {
        float4 r;
        float* rp = &r.x;
        #pragma unroll
        for (int i = 0; i < 4; i++) {
            int px = 64 * xc + 16 * xg + 4 * q + i;
            float sx = (px + 0.5f) * 0.25f - 0.5f;
            int   x0 = (int)floorf(sx);
            float fx = sx - (float)x0;
            int l0 = x0 - (16 * xc - 1);
            l0 = min(17, max(0, l0));
            int l1 = min(17, l0 + 1);
            float t0 = sf[0][oc][l0]; float t1 = sf[0][oc][l1];
            float b0 = sf[1][oc][l0]; float b1 = sf[1][oc][l1];
            float top = t0 + fx * (t1 - t0);
            float bot = b0 + fx * (b1 - b0);
            rp[i] = top + fy * (bot - top);
        }
        *(float4*)(out + obase + 4 * q) = r;
        float4 xv = *(const float4*)(xr + 4 * q);
        float d0 = r.x - xv.x, d1 = r.y - xv.y, d2 = r.z - xv.z, d3 = r.w - xv.w;
        ls = fmaf(d0, d0, ls); ls = fmaf(d1, d1, ls);
        ls = fmaf(d2, d2, ls); ls = fmaf(d3, d3, ls);
    }
    #pragma unroll
    for (int off = 16; off > 0; off >>= 1) ls += __shfl_down_sync(0xffffffffu, ls, off);
    __shared__ float sp[8];
    if ((t & 31) == 0) sp[t >> 5] = ls;
    __syncthreads();
    if (t == 0) {
        float s = 0.f;
        #pragma unroll
        for (int w = 0; w < 8; w++) s += sp[w];
        atomicAdd(&g_acc[0], (double)s);
    }
}

__global__ void k_finalize(float* __restrict__ out)
{
    double rl = g_acc[0] / (double)N_RECON;
    double vq = g_acc[1] * 1.25 / (double)N_Q;   // (1+BETA)*mean((q-z)^2)
    out[OFF_LOSS + 0] = (float)(rl + vq);
    out[OFF_LOSS + 1] = (float)rl;
    out[OFF_LOSS + 2] = (float)vq;
}

// ---------------- launch ----------------
extern "C" void kernel_launch(void* const* d_in, const int* in_sizes, int n_in,
                              void* d_out, int out_size)
{
    const float* x      = (const float*)d_in[0];
    const float* w_spec = (const float*)d_in[1];
    const float* b_spec = (const float*)d_in[2];
    const float* w_e1   = (const float*)d_in[3];
    const float* b_e1   = (const float*)d_in[4];
    const float* w_e2   = (const float*)d_in[5];
    const float* b_e2   = (const float*)d_in[6];
    const float* w_proj = (const float*)d_in[7];
    const float* b_proj = (const float*)d_in[8];
    const float* cb     = (const float*)d_in[9];
    const float* w_rec  = (const float*)d_in[10];
    const float* b_rec  = (const float*)d_in[11];
    const float* w_fin  = (const float*)d_in[12];
    const float* b_fin  = (const float*)d_in[13];
    float* out = (float*)d_out;

    float *s2, *s3, *tok;
    float *wt_f, *wt_e2, *wt_proj;
    cudaGetSymbolAddress((void**)&s2,   g_s2);
    cudaGetSymbolAddress((void**)&s3,   g_s3);
    cudaGetSymbolAddress((void**)&tok,  g_tok);
    cudaGetSymbolAddress((void**)&wt_f,    g_wt_f);
    cudaGetSymbolAddress((void**)&wt_e2,   g_wt_e2);
    cudaGetSymbolAddress((void**)&wt_proj, g_wt_proj);

    k_init<<<1, 1>>>();

    // weight prep
    k_transpose_all<<<(N_TRANS_ALL + 255) / 256, 256>>>(w_e1, w_e2, w_proj, w_rec, w_fin, cb);
    k_comb<<<dim3(64, 9), 128>>>(w_spec);
    k_tapbias<<<9, 128>>>(b_spec);
    k_cnorm<<<4, 256>>>(cb);
    k_ptab<<<dim3(1025, 9), 128>>>(cb);

    // fused spec+e1: 3x3 s2, 64->128, 256->128 (on x directly)
    k_conv_t<3,2,4,128,true,true><<<dim3(2, 128, 16), 256>>>(x, wt_f, b_e1, s2,
                                                             64, 256, 256, 128, 128, 128, 2);
    // e2: 3x3 s2, 128->256, 128->64
    k_conv_t<3,2,4,128,true,false><<<dim3(2, 64, 16), 256>>>(s2, wt_e2, b_e2, s3,
                                                             128, 128, 128, 64, 64, 256, 1);
    // proj: 1x1, 256->128, 64x64
    k_conv_t<1,1,16,128,false,false><<<dim3(1, 64, 16), 256>>>(s3, wt_proj, b_proj, tok,
                                                               256, 64, 64, 64, 64, 128, 1);
    // VQ argmin + indices + quantized output + vq loss (fused, 16 tok/block)
    k_vq<<<4096, 256>>>(cb, out);
    // rec conv via codeword table + fin 1x1 fused -> g_fin
    k_rec_fin<<<dim3(64, 16), 128>>>(b_rec, b_fin);
    // bilinear 4x upsample + recon output + recon loss
    k_upsample<<<dim3(4, 256, 16), 256>>>(x, out);

    k_finalize<<<1, 1>>>(out);
}

// round 17
// speedup vs baseline: 1.0553x; 1.0553x over previous
#include <cuda_runtime.h>
#include <math.h>

// ---------------- output layout (float32, tuple order) ----------------
#define N_RECON   (16ULL*64*256*256)          // 67108864
#define OFF_Q     (N_RECON)
#define N_Q       (16ULL*4096*128)            // 8388608
#define OFF_IDX   (OFF_Q + N_Q)               // 75497472
#define N_IDX     (16ULL*4096)
#define OFF_LOSS  (OFF_IDX + N_IDX)           // 75563008

// ---------------- scratch (device globals; no allocation) ----------------
__device__ float g_s2[16ULL*128*128*128];   // fused(spec+e1) out [16,128,128,128]
__device__ float g_s3[16ULL*256*64*64];     // e2 out             [16,256,64,64]
__device__ float g_tok[16ULL*128*64*64];    // proj out (tokens, NCHW)
__device__ float g_fin[16ULL*64*64*64];     // final 1x1 conv at low res
__device__ int   g_idx[16*4096];
__device__ float g_wt_e1[128*9*128];        // e1 transposed [(h,ky,kx)][oc]
__device__ float g_wt_f[64*9*128];          // fused weights [(ic,ky,kx)][oc]
__device__ float g_tb[9*128];               // spec-bias tap table [kyx][oc]
__device__ float g_wt_e2[128*9*256];
__device__ float g_wt_proj[256*128];
__device__ float g_wt_rec[128*9*128];
__device__ float g_wt_fin[128*64];
__device__ float g_ct[128*1024];            // codebook transposed [k][j]
__device__ float g_cnorm[1024];
__device__ float g_ptab[1025ULL*9*128];     // rec-conv codeword table; row 1024 = zeros
__device__ double g_acc[2];                 // [0]=recon sq sum, [1]=vq sq sum

// ---------------- small helpers ----------------
__global__ void k_init() { g_acc[0] = 0.0; g_acc[1] = 0.0; }

// all weight transposes in one grid-stride launch: dst[r*Cout+oc] = src[oc*R+r]
__global__ void k_transpose_all(const float* __restrict__ w_e1, const float* __restrict__ w_e2,
                                const float* __restrict__ w_proj, const float* __restrict__ w_rec,
                                const float* __restrict__ w_fin, const float* __restrict__ cb)
{
    int i = blockIdx.x * blockDim.x + threadIdx.x;
    if (i < 147456) { int oc=i/1152, r=i-oc*1152; g_wt_e1[(size_t)r*128+oc]=w_e1[i]; return; }
    i -= 147456;
    if (i < 294912) { int oc=i/1152, r=i-oc*1152; g_wt_e2[(size_t)r*256+oc]=w_e2[i]; return; }
    i -= 294912;
    if (i < 32768)  { int oc=i/256,  r=i-oc*256;  g_wt_proj[(size_t)r*128+oc]=w_proj[i]; return; }
    i -= 32768;
    if (i < 147456) { int oc=i/1152, r=i-oc*1152; g_wt_rec[(size_t)r*128+oc]=w_rec[i]; return; }
    i -= 147456;
    if (i < 8192)   { int oc=i/128,  r=i-oc*128;  g_wt_fin[(size_t)r*64+oc]=w_fin[i]; return; }
    i -= 8192;
    if (i < 131072) { int oc=i/128,  r=i-oc*128;  g_ct[(size_t)r*1024+oc]=cb[i]; }
}
#define N_TRANS_ALL (147456+294912+32768+147456+8192+131072)

__global__ void k_comb(const float* __restrict__ w_spec)
{
    int ic = blockIdx.x, kyx = blockIdx.y, oc = threadIdx.x;
    float s = 0.f;
    #pragma unroll 8
    for (int h = 0; h < 128; h++)
        s = fmaf(g_wt_e1[(size_t)(h * 9 + kyx) * 128 + oc], w_spec[h * 64 + ic], s);
    g_wt_f[(size_t)(ic * 9 + kyx) * 128 + oc] = s;
}

__global__ void k_tapbias(const float* __restrict__ b_spec)
{
    int kyx = blockIdx.x, oc = threadIdx.x;
    float s = 0.f;
    #pragma unroll 8
    for (int h = 0; h < 128; h++)
        s = fmaf(g_wt_e1[(size_t)(h * 9 + kyx) * 128 + oc], b_spec[h], s);
    g_tb[kyx * 128 + oc] = s;
}

__global__ void k_cnorm(const float* __restrict__ cb)
{
    int j = blockIdx.x * blockDim.x + threadIdx.x;
    if (j < 1024) {
        float s = 0.f;
        #pragma unroll 8
        for (int k = 0; k < 128; k++) { float v = cb[j*128+k]; s = fmaf(v, v, s); }
        g_cnorm[j] = s;
    }
}

// rec-conv codeword table
__global__ void k_ptab(const float* __restrict__ cb)
{
    int j = blockIdx.x, kyx = blockIdx.y, oc = threadIdx.x;
    float s = 0.f;
    if (j < 1024) {
        #pragma unroll 8
        for (int c = 0; c < 128; c++)
            s = fmaf(g_wt_rec[(size_t)(c * 9 + kyx) * 128 + oc], cb[j * 128 + c], s);
    }
    g_ptab[((size_t)j * 9 + kyx) * 128 + oc] = s;
}

// ---------------- smem-tiled direct conv: 8 oc x 8 px per thread ----------------
template<int K, int S, int CHUNK, int TOC, bool RELU, bool FUSEB>
__global__ void k_conv_t(const float* __restrict__ in, const float* __restrict__ wt,
                         const float* __restrict__ bias, float* __restrict__ out,
                         int Cin, int Hin, int Win, int Hout, int Wout, int Cout, int nxc)
{
    constexpr int PAD   = (K == 3) ? 1 : 0;
    constexpr int SPAN  = 63 * S + K;
    constexpr int SPAD  = (SPAN + 3) & ~3;
    constexpr int VSPAN = 7 * S + K;
    constexpr int OCW   = TOC / 8;              // threads along oc (8 oc each)
    constexpr int NT    = OCW * 8;              // block size (=128 for TOC=128)

    __shared__ __align__(16) float s_in[CHUNK][K][SPAD];
    __shared__ __align__(16) float s_w[CHUNK * K * K][TOC];

    const int t    = threadIdx.x;
    const int ocg  = t % OCW;
    const int px0  = (t / OCW) * 8;

    const int xc    = blockIdx.x % nxc;
    const int ocblk = blockIdx.x / nxc;
    const int oy    = blockIdx.y;
    const int b     = blockIdx.z;

    const int ix0 = xc * 64 * S - PAD;
    const int iy0 = oy * S - PAD;

    float acc[8][8];                            // [oc j][pixel p]
    #pragma unroll
    for (int j = 0; j < 8; j++)
        #pragma unroll
        for (int p = 0; p < 8; p++) acc[j][p] = 0.f;

    const int nchunk = Cin / CHUNK;
    for (int cc = 0; cc < nchunk; cc++) {
        const int ic0 = cc * CHUNK;
        __syncthreads();
        for (int idx = t; idx < CHUNK * K * SPAN; idx += NT) {
            int ic  = idx / (K * SPAN);
            int rem = idx - ic * (K * SPAN);
            int ky  = rem / SPAN;
            int j   = rem - ky * SPAN;
            int iy = iy0 + ky;
            int ix = ix0 + j;
            float v = 0.f;
            if (iy >= 0 && iy < Hin && ix >= 0 && ix < Win)
                v = in[(((size_t)b * Cin + ic0 + ic) * Hin + iy) * Win + ix];
            s_in[ic][ky][j] = v;
        }
        const float* wsrc = wt + (size_t)(ic0 * K * K) * Cout + ocblk * TOC;
        for (int idx = t; idx < CHUNK * K * K * (TOC / 4); idx += NT) {
            int rr = idx / (TOC / 4);
            int c4 = idx - rr * (TOC / 4);
            float4 w = *(const float4*)(wsrc + (size_t)rr * Cout + c4 * 4);
            *(float4*)&s_w[rr][c4 * 4] = w;
        }
        __syncthreads();

        #pragma unroll
        for (int ic = 0; ic < CHUNK; ic++) {
            #pragma unroll
            for (int ky = 0; ky < K; ky++) {
                float v[VSPAN];
                #pragma unroll
                for (int i = 0; i < VSPAN; i++) v[i] = s_in[ic][ky][px0 * S + i];
                #pragma unroll
                for (int kx = 0; kx < K; kx++) {
                    const float* wr = &s_w[(ic * K + ky) * K + kx][8 * ocg];
                    float4 wA = *(const float4*)(wr);
                    float4 wB = *(const float4*)(wr + 4);
                    #pragma unroll
                    for (int p = 0; p < 8; p++) {
                        float xv = v[p * S + kx];
                        acc[0][p] = fmaf(wA.x, xv, acc[0][p]);
                        acc[1][p] = fmaf(wA.y, xv, acc[1][p]);
                        acc[2][p] = fmaf(wA.z, xv, acc[2][p]);
                        acc[3][p] = fmaf(wA.w, xv, acc[3][p]);
                        acc[4][p] = fmaf(wB.x, xv, acc[4][p]);
                        acc[5][p] = fmaf(wB.y, xv, acc[5][p]);
                        acc[6][p] = fmaf(wB.z, xv, acc[6][p]);
                        acc[7][p] = fmaf(wB.w, xv, acc[7][p]);
                    }
                }
            }
        }
    }

    #pragma unroll
    for (int j = 0; j < 8; j++) {
        int oc = ocblk * TOC + ocg * 8 + j;
        float bv = bias[oc];
        float lsub = 0.f;
        if (FUSEB) {
            float t00 = g_tb[0*128+oc], t01 = g_tb[1*128+oc], t02 = g_tb[2*128+oc];
            float t10 = g_tb[3*128+oc], t11 = g_tb[4*128+oc], t12 = g_tb[5*128+oc];
            float t20 = g_tb[6*128+oc], t21 = g_tb[7*128+oc], t22 = g_tb[8*128+oc];
            float add = t10+t11+t12 + t20+t21+t22;
            lsub = t10 + t20;
            if (oy > 0) { add += t00+t01+t02; lsub += t00; }
            bv += add;
        }
        size_t o = (((size_t)b * Cout + oc) * Hout + oy) * Wout + xc * 64 + px0;
        float4 r0, r1;
        r0.x = acc[j][0] + bv;
        r0.y = acc[j][1] + bv;
        r0.z = acc[j][2] + bv;
        r0.w = acc[j][3] + bv;
        r1.x = acc[j][4] + bv;
        r1.y = acc[j][5] + bv;
        r1.z = acc[j][6] + bv;
        r1.w = acc[j][7] + bv;
        if (FUSEB && xc == 0 && px0 == 0) r0.x -= lsub;
        if (RELU) {
            r0.x = fmaxf(r0.x, 0.f);
            r0.y = fmaxf(r0.y, 0.f);
            r0.z = fmaxf(r0.z, 0.f);
            r0.w = fmaxf(r0.w, 0.f);
            r1.x = fmaxf(r1.x, 0.f);
            r1.y = fmaxf(r1.y, 0.f);
            r1.z = fmaxf(r1.z, 0.f);
            r1.w = fmaxf(r1.w, 0.f);
        }
        *(float4*)(out + o)     = r0;
        *(float4*)(out + o + 4) = r1;
    }
}

// ---------------- VQ fused: 16 tokens/block, 256 thr, 4 codes/thread ----------------
// argmin_j (||C_j||^2 - 2 z.C_j); writes idx + quantized outputs + vq loss.
__global__ void k_vq(const float* __restrict__ cb, float* __restrict__ out)
{
    int g  = blockIdx.x;            // 0..4095
    int b  = g >> 8;
    int p0 = (g & 255) << 4;        // 16 tokens, same y row (p0 mult of 16)
    int t  = threadIdx.x;           // 0..255
    int c4 = t * 4;                 // first code of this thread

    __shared__ __align__(16) float zs[16][132];   // [token][k]; 528 B row stride
    {
        int ch = t & 127, ph = (t >> 7) * 8;    // 8 tokens per half
        int y = p0 >> 6, x0 = (p0 & 63) + ph;
        const float* src = g_tok + (((size_t)(b * 128 + ch)) * 64 + y) * 64 + x0;
        #pragma unroll
        for (int p = 0; p < 8; p++) zs[ph + p][ch] = src[p];
    }
    __syncthreads();

    float acc[16][4];
    #pragma unroll
    for (int p = 0; p < 16; p++)
        #pragma unroll
        for (int j = 0; j < 4; j++) acc[p][j] = 0.f;

    for (int k = 0; k < 128; k += 4) {
        float4 w0 = *(const float4*)(g_ct + (size_t)(k+0) * 1024 + c4);
        float4 w1 = *(const float4*)(g_ct + (size_t)(k+1) * 1024 + c4);
        float4 w2 = *(const float4*)(g_ct + (size_t)(k+2) * 1024 + c4);
        float4 w3 = *(const float4*)(g_ct + (size_t)(k+3) * 1024 + c4);
        #pragma unroll
        for (int p = 0; p < 16; p++) {
            float4 z = *(const float4*)&zs[p][k];
            acc[p][0] = fmaf(w0.x, z.x, acc[p][0]); acc[p][1] = fmaf(w0.y, z.x, acc[p][1]);
            acc[p][2] = fmaf(w0.z, z.x, acc[p][2]); acc[p][3] = fmaf(w0.w, z.x, acc[p][3]);
            acc[p][0] = fmaf(w1.x, z.y, acc[p][0]); acc[p][1] = fmaf(w1.y, z.y, acc[p][1]);
            acc[p][2] = fmaf(w1.z, z.y, acc[p][2]); acc[p][3] = fmaf(w1.w, z.y, acc[p][3]);
            acc[p][0] = fmaf(w2.x, z.z, acc[p][0]); acc[p][1] = fmaf(w2.y, z.z, acc[p][1]);
            acc[p][2] = fmaf(w2.z, z.z, acc[p][2]); acc[p][3] = fmaf(w2.w, z.z, acc[p][3]);
            acc[p][0] = fmaf(w3.x, z.w, acc[p][0]); acc[p][1] = fmaf(w3.y, z.w, acc[p][1]);
            acc[p][2] = fmaf(w3.z, z.w, acc[p][2]); acc[p][3] = fmaf(w3.w, z.w, acc[p][3]);
        }
    }

    float cn[4];
    #pragma unroll
    for (int j = 0; j < 4; j++) cn[j] = g_cnorm[c4 + j];

    __shared__ float s_bd[8][16];
    __shared__ int   s_bi[8][16];
    __shared__ int   s_win[16];
    #pragma unroll
    for (int p = 0; p < 16; p++) {
        float bd = 3.4e38f; int bi = 0;
        #pragma unroll
        for (int j = 0; j < 4; j++) {
            float d = cn[j] - 2.f * acc[p][j];
            if (d < bd) { bd = d; bi = c4 + j; }
        }
        #pragma unroll
        for (int off = 16; off > 0; off >>= 1) {
            float od = __shfl_down_sync(0xffffffffu, bd, off);
            int   oi = __shfl_down_sync(0xffffffffu, bi, off);
            if (od < bd || (od == bd && oi < bi)) { bd = od; bi = oi; }
        }
        if ((t & 31) == 0) { s_bd[t >> 5][p] = bd; s_bi[t >> 5][p] = bi; }
    }
    __syncthreads();
    if (t < 16) {
        float bd = s_bd[0][t]; int bi = s_bi[0][t];
        #pragma unroll
        for (int w = 1; w < 8; w++) {
            float od = s_bd[w][t]; int oi = s_bi[w][t];
            if (od < bd || (od == bd && oi < bi)) { bd = od; bi = oi; }
        }
        int tokid = b * 4096 + p0 + t;
        g_idx[tokid] = bi;
        out[OFF_IDX + tokid] = (float)bi;
        s_win[t] = bi;
    }
    __syncthreads();

    // gather quantized rows, write output block, vq-loss partial
    float ls = 0.f;
    {
        int ch = t & 127, ph = (t >> 7) * 8;
        #pragma unroll
        for (int p = 0; p < 8; p++) {
            int pp = ph + p;
            float q = cb[(size_t)s_win[pp] * 128 + ch];
            out[OFF_Q + ((size_t)(b * 4096 + p0 + pp)) * 128 + ch] = q;
            float d = q - zs[pp][ch];
            ls = fmaf(d, d, ls);
        }
    }
    #pragma unroll
    for (int off = 16; off > 0; off >>= 1) ls += __shfl_down_sync(0xffffffffu, ls, off);
    __shared__ float sp[8];
    if ((t & 31) == 0) sp[t >> 5] = ls;
    __syncthreads();
    if (t == 0) {
        float s = 0.f;
        #pragma unroll
        for (int w = 0; w < 8; w++) s += sp[w];
        atomicAdd(&g_acc[1], (double)s);
    }
}

// ---------------- rec conv (codeword table) + fin 1x1 fused -> g_fin ----------------
// grid (64 y, 16 b), block 128. rec_s rows 68 floats (272 B, 16B-aligned stride).
__global__ void k_rec_fin(const float* __restrict__ b_rec, const float* __restrict__ b_fin)
{
    int t = threadIdx.x, y = blockIdx.x, b = blockIdx.y;
    __shared__ int sidx[3][66];                    // x in [-1,64], sentinel 1024
    __shared__ __align__(16) float rec_s[128][68]; // relu'd rec row [c][x]
    for (int i = t; i < 3 * 66; i += 128) {
        int r  = i / 66;
        int rx = i - r * 66 - 1;
        int ry = y - 1 + r;
        sidx[r][rx + 1] = (ry >= 0 && ry < 64 && rx >= 0 && rx < 64)
                          ? g_idx[b * 4096 + ry * 64 + rx] : 1024;
    }
    __syncthreads();
    // phase 1: rec row for channel t
    {
        float bv = b_rec[t];
        for (int x = 0; x < 64; x += 2) {
            float a0 = bv, a1 = bv;
            #pragma unroll
            for (int ky = 0; ky < 3; ky++) {
                #pragma unroll
                for (int kx = 0; kx < 3; kx++) {
                    int j0 = sidx[ky][x + kx];
                    int j1 = sidx[ky][x + 1 + kx];
                    a0 += g_ptab[((size_t)j0 * 9 + ky * 3 + kx) * 128 + t];
                    a1 += g_ptab[((size_t)j1 * 9 + ky * 3 + kx) * 128 + t];
                }
            }
            rec_s[t][x]     = fmaxf(a0, 0.f);
            rec_s[t][x + 1] = fmaxf(a1, 0.f);
        }
    }
    __syncthreads();
    // phase 2: fin 1x1 (128->64) on this row; thread: ocf = t&63, x-half = (t>>6)*32
    {
        int ocf = t & 63, xh = (t >> 6) * 32;
        float a[32];
        float bv = b_fin[ocf];
        #pragma unroll
        for (int i = 0; i < 32; i++) a[i] = bv;
        for (int c = 0; c < 128; c++) {
            float w = g_wt_fin[c * 64 + ocf];
            #pragma unroll
            for (int q = 0; q < 8; q++) {
                float4 r = *(const float4*)&rec_s[c][xh + 4 * q];
                a[4*q+0] = fmaf(w, r.x, a[4*q+0]);
                a[4*q+1] = fmaf(w, r.y, a[4*q+1]);
                a[4*q+2] = fmaf(w, r.z, a[4*q+2]);
                a[4*q+3] = fmaf(w, r.w, a[4*q+3]);
            }
        }
        float* dst = g_fin + (((size_t)(b * 64 + ocf)) * 64 + y) * 64 + xh;
        #pragma unroll
        for (int q = 0; q < 8; q++)
            *(float4*)(dst + 4 * q) = make_float4(a[4*q], a[4*q+1], a[4*q+2], a[4*q+3]);
    }
}

// ---------------- bilinear 4x upsample of g_fin (+recon loss) ----------------
__global__ void k_upsample(const float* __restrict__ x, float* __restrict__ out)
{
    int t  = threadIdx.x;
    int oc = t & 63;
    int xg = t >> 6;
    int xc = blockIdx.x, oy = blockIdx.y, b = blockIdx.z;

    float sy = (oy + 0.5f) * 0.25f - 0.5f;
    int   y0 = (int)floorf(sy);
    float fy = sy - (float)y0;
    int y0c = min(63, max(0, y0));
    int y1c = min(63, max(0, y0 + 1));

    __shared__ float sf[2][64][19];
    for (int idx = t; idx < 2 * 64 * 18; idx += 256) {
        int row = idx / (64 * 18);
        int rem = idx - row * 64 * 18;
        int c   = rem / 18;
        int sx  = rem - c * 18;
        int gx = min(63, max(0, 16 * xc - 1 + sx));
        int gy = row ? y1c : y0c;
        sf[row][c][sx] = g_fin[(((size_t)b * 64 + c) * 64 + gy) * 64 + gx];
    }
    __syncthreads();

    float ls = 0.f;
    size_t obase = (((size_t)b * 64 + oc) * 256 + oy) * 256 + 64 * xc + 16 * xg;
    const float* xr = x + obase;
    #pragma unroll
    for (int q = 0; q < 4; q++) {
        float4 r;
        float* rp = &r.x;
        #pragma unroll
        for (int i = 0; i < 4; i++) {
            int px = 64 * xc + 16 * xg + 4 * q + i;
            float sx = (px + 0.5f) * 0.25f - 0.5f;
            int   x0 = (int)floorf(sx);
            float fx = sx - (float)x0;
            int l0 = x0 - (16 * xc - 1);
            l0 = min(17, max(0, l0));
            int l1 = min(17, l0 + 1);
            float t0 = sf[0][oc][l0]; float t1 = sf[0][oc][l1];
            float b0 = sf[1][oc][l0]; float b1 = sf[1][oc][l1];
            float top = t0 + fx * (t1 - t0);
            float bot = b0 + fx * (b1 - b0);
            rp[i] = top + fy * (bot - top);
        }
        *(float4*)(out + obase + 4 * q) = r;
        float4 xv = *(const float4*)(xr + 4 * q);
        float d0 = r.x - xv.x, d1 = r.y - xv.y, d2 = r.z - xv.z, d3 = r.w - xv.w;
        ls = fmaf(d0, d0, ls); ls = fmaf(d1, d1, ls);
        ls = fmaf(d2, d2, ls); ls = fmaf(d3, d3, ls);
    }
    #pragma unroll
    for (int off = 16; off > 0; off >>= 1) ls += __shfl_down_sync(0xffffffffu, ls, off);
    __shared__ float sp[8];
    if ((t & 31) == 0) sp[t >> 5] = ls;
    __syncthreads();
    if (t == 0) {
        float s = 0.f;
        #pragma unroll
        for (int w = 0; w < 8; w++) s += sp[w];
        atomicAdd(&g_acc[0], (double)s);
    }
}

__global__ void k_finalize(float* __restrict__ out)
{
    double rl = g_acc[0] / (double)N_RECON;
    double vq = g_acc[1] * 1.25 / (double)N_Q;   // (1+BETA)*mean((q-z)^2)
    out[OFF_LOSS + 0] = (float)(rl + vq);
    out[OFF_LOSS + 1] = (float)rl;
    out[OFF_LOSS + 2] = (float)vq;
}

// ---------------- launch ----------------
extern "C" void kernel_launch(void* const* d_in, const int* in_sizes, int n_in,
                              void* d_out, int out_size)
{
    const float* x      = (const float*)d_in[0];
    const float* w_spec = (const float*)d_in[1];
    const float* b_spec = (const float*)d_in[2];
    const float* w_e1   = (const float*)d_in[3];
    const float* b_e1   = (const float*)d_in[4];
    const float* w_e2   = (const float*)d_in[5];
    const float* b_e2   = (const float*)d_in[6];
    const float* w_proj = (const float*)d_in[7];
    const float* b_proj = (const float*)d_in[8];
    const float* cb     = (const float*)d_in[9];
    const float* w_rec  = (const float*)d_in[10];
    const float* b_rec  = (const float*)d_in[11];
    const float* w_fin  = (const float*)d_in[12];
    const float* b_fin  = (const float*)d_in[13];
    float* out = (float*)d_out;

    float *s2, *s3, *tok;
    float *wt_f, *wt_e2, *wt_proj;
    cudaGetSymbolAddress((void**)&s2,   g_s2);
    cudaGetSymbolAddress((void**)&s3,   g_s3);
    cudaGetSymbolAddress((void**)&tok,  g_tok);
    cudaGetSymbolAddress((void**)&wt_f,    g_wt_f);
    cudaGetSymbolAddress((void**)&wt_e2,   g_wt_e2);
    cudaGetSymbolAddress((void**)&wt_proj, g_wt_proj);

    k_init<<<1, 1>>>();

    // weight prep
    k_transpose_all<<<(N_TRANS_ALL + 255) / 256, 256>>>(w_e1, w_e2, w_proj, w_rec, w_fin, cb);
    k_comb<<<dim3(64, 9), 128>>>(w_spec);
    k_tapbias<<<9, 128>>>(b_spec);
    k_cnorm<<<4, 256>>>(cb);
    k_ptab<<<dim3(1025, 9), 128>>>(cb);

    // fused spec+e1: 3x3 s2, 64->128, 256->128 (on x directly); block 128 thr
    k_conv_t<3,2,4,128,true,true><<<dim3(2, 128, 16), 128>>>(x, wt_f, b_e1, s2,
                                                             64, 256, 256, 128, 128, 128, 2);
    // e2: 3x3 s2, 128->256, 128->64
    k_conv_t<3,2,4,128,true,false><<<dim3(2, 64, 16), 128>>>(s2, wt_e2, b_e2, s3,
                                                             128, 128, 128, 64, 64, 256, 1);
    // proj: 1x1, 256->128, 64x64
    k_conv_t<1,1,16,128,false,false><<<dim3(1, 64, 16), 128>>>(s3, wt_proj, b_proj, tok,
                                                               256, 64, 64, 64, 64, 128, 1);
    // VQ argmin + indices + quantized output + vq loss (fused, 16 tok/block)
    k_vq<<<4096, 256>>>(cb, out);
    // rec conv via codeword table + fin 1x1 fused -> g_fin
    k_rec_fin<<<dim3(64, 16), 128>>>(b_rec, b_fin);
    // bilinear 4x upsample + recon output + recon loss
    k_upsample<<<dim3(4, 256, 16), 256>>>(x, out);

    k_finalize<<<1, 1>>>(out);
}